// round 1
// baseline (speedup 1.0000x reference)
#include <cuda_runtime.h>
#include <math.h>

#define H 1024
#define S 2048
#define VOCAB 50257
#define H3 3072
#define H2 2048

// ---------------- scratch (__device__ globals; no allocation allowed) ------
__device__ float g_x0[H2];        // [emb[word], last_context]
__device__ float g_gi0[H3];
__device__ float g_gh0[H3];
__device__ float g_h0[H];
__device__ float g_gi1[H3];
__device__ float g_gh1[H3];
__device__ float g_h1[H];
__device__ float g_energ[S];
__device__ float g_ctx_part[32 * H];
__device__ float g_ctx[H];
__device__ float g_xout[H2];      // [h1, context]
__device__ float g_lse[1];

__device__ __forceinline__ float sigmoidf_(float x) {
    return 1.0f / (1.0f + expf(-x));
}

// ---------------- kernels --------------------------------------------------

// x0 = concat(emb[word], last_context)
__global__ void k_assemble_x0(const int* __restrict__ word,
                              const float* __restrict__ emb,
                              const float* __restrict__ last_context) {
    int i = blockIdx.x * blockDim.x + threadIdx.x;
    if (i >= H2) return;
    int w = word[0];
    g_x0[i] = (i < H) ? emb[(size_t)w * H + i] : last_context[i - H];
}

// y[r] = dot(W[r,:], x) + b[r]   (warp per row, float4)
__global__ void k_matvec(const float* __restrict__ W,
                         const float* __restrict__ x,
                         const float* __restrict__ b,
                         float* __restrict__ y,
                         int rows, int n) {
    int warp = (blockIdx.x * blockDim.x + threadIdx.x) >> 5;
    int lane = threadIdx.x & 31;
    if (warp >= rows) return;
    const float4* w4 = reinterpret_cast<const float4*>(W + (size_t)warp * n);
    const float4* x4 = reinterpret_cast<const float4*>(x);
    int n4 = n >> 2;
    float sum = 0.0f;
    #pragma unroll 4
    for (int i = lane; i < n4; i += 32) {
        float4 a = w4[i];
        float4 c = x4[i];
        sum += a.x * c.x + a.y * c.y + a.z * c.z + a.w * c.w;
    }
    #pragma unroll
    for (int o = 16; o > 0; o >>= 1)
        sum += __shfl_xor_sync(0xFFFFFFFFu, sum, o);
    if (lane == 0) y[warp] = sum + (b ? b[warp] : 0.0f);
}

// GRU gate combine: h = (1-z)*n + z*h_prev
__global__ void k_gru_combine(const float* __restrict__ gi,
                              const float* __restrict__ gh,
                              const float* __restrict__ hprev,
                              float* __restrict__ hout,
                              float* __restrict__ hcopy) {
    int j = blockIdx.x * blockDim.x + threadIdx.x;
    if (j >= H) return;
    float r = sigmoidf_(gi[j] + gh[j]);
    float z = sigmoidf_(gi[H + j] + gh[H + j]);
    float n = tanhf(gi[2 * H + j] + r * gh[2 * H + j]);
    float h = (1.0f - z) * n + z * hprev[j];
    hout[j] = h;
    hcopy[j] = h;
}

// softmax over S=2048 energies -> attention weights (one block of 1024)
__global__ void k_attn_softmax(float* __restrict__ wout) {
    __shared__ float red[1024];
    int t = threadIdx.x;
    float a = g_energ[t];
    float b = g_energ[t + 1024];
    red[t] = fmaxf(a, b);
    __syncthreads();
    for (int s = 512; s > 0; s >>= 1) {
        if (t < s) red[t] = fmaxf(red[t], red[t + s]);
        __syncthreads();
    }
    float m = red[0];
    __syncthreads();
    float ea = expf(a - m), eb = expf(b - m);
    red[t] = ea + eb;
    __syncthreads();
    for (int s = 512; s > 0; s >>= 1) {
        if (t < s) red[t] += red[t + s];
        __syncthreads();
    }
    float inv = 1.0f / red[0];
    wout[t] = ea * inv;
    wout[t + 1024] = eb * inv;
}

// partial context: block = s-chunk of 64, thread = d
__global__ void k_ctx_partial(const float* __restrict__ enc,
                              const float* __restrict__ w) {
    int d = threadIdx.x;
    int s0 = blockIdx.x * 64;
    float acc = 0.0f;
    #pragma unroll 8
    for (int s = s0; s < s0 + 64; ++s)
        acc += w[s] * enc[(size_t)s * H + d];
    g_ctx_part[blockIdx.x * H + d] = acc;
}

// reduce 32 partials -> context; also assemble xout = [h1, context]
__global__ void k_ctx_reduce(float* __restrict__ ctx_out) {
    int d = blockIdx.x * blockDim.x + threadIdx.x;
    if (d >= H) return;
    float acc = 0.0f;
    #pragma unroll
    for (int c = 0; c < 32; ++c)
        acc += g_ctx_part[c * H + d];
    g_ctx[d] = acc;
    ctx_out[d] = acc;
    g_xout[d] = g_h1[d];
    g_xout[H + d] = acc;
}

// single-block logsumexp over VOCAB logits
__global__ void k_lse(const float* __restrict__ logits) {
    __shared__ float red[1024];
    int t = threadIdx.x;
    float m = -INFINITY;
    for (int v = t; v < VOCAB; v += 1024) m = fmaxf(m, logits[v]);
    red[t] = m;
    __syncthreads();
    for (int s = 512; s > 0; s >>= 1) {
        if (t < s) red[t] = fmaxf(red[t], red[t + s]);
        __syncthreads();
    }
    m = red[0];
    __syncthreads();
    float sum = 0.0f;
    for (int v = t; v < VOCAB; v += 1024) sum += expf(logits[v] - m);
    red[t] = sum;
    __syncthreads();
    for (int s = 512; s > 0; s >>= 1) {
        if (t < s) red[t] += red[t + s];
        __syncthreads();
    }
    if (t == 0) g_lse[0] = m + logf(red[0]);
}

__global__ void k_finalize(float* __restrict__ logits) {
    int v = blockIdx.x * blockDim.x + threadIdx.x;
    if (v < VOCAB) logits[v] -= g_lse[0];
}

// ---------------- launch ---------------------------------------------------

extern "C" void kernel_launch(void* const* d_in, const int* in_sizes, int n_in,
                              void* d_out, int out_size) {
    const int*   word      = (const int*)  d_in[0];
    const float* last_ctx  = (const float*)d_in[1];
    const float* last_hid  = (const float*)d_in[2];   // (2,1,H)
    const float* enc       = (const float*)d_in[3];   // (S,1,H)
    const float* emb       = (const float*)d_in[4];
    const float* W_ih0     = (const float*)d_in[5];
    const float* W_hh0     = (const float*)d_in[6];
    const float* b_ih0     = (const float*)d_in[7];
    const float* b_hh0     = (const float*)d_in[8];
    const float* W_ih1     = (const float*)d_in[9];
    const float* W_hh1     = (const float*)d_in[10];
    const float* b_ih1     = (const float*)d_in[11];
    const float* b_hh1     = (const float*)d_in[12];
    const float* W_out     = (const float*)d_in[13];
    const float* b_out     = (const float*)d_in[14];

    float* out       = (float*)d_out;
    float* out_logit = out;                     // [0, V)
    float* out_ctx   = out + VOCAB;             // [V, V+H)
    float* out_h0    = out + VOCAB + H;         // h0
    float* out_h1    = out + VOCAB + 2 * H;     // h1
    float* out_attn  = out + VOCAB + 3 * H;     // [.., ..+S)

    // pointers to __device__ scratch
    float *px0, *pgi0, *pgh0, *ph0, *pgi1, *pgh1, *ph1, *peng, *pxout;
    cudaGetSymbolAddress((void**)&px0,   g_x0);
    cudaGetSymbolAddress((void**)&pgi0,  g_gi0);
    cudaGetSymbolAddress((void**)&pgh0,  g_gh0);
    cudaGetSymbolAddress((void**)&ph0,   g_h0);
    cudaGetSymbolAddress((void**)&pgi1,  g_gi1);
    cudaGetSymbolAddress((void**)&pgh1,  g_gh1);
    cudaGetSymbolAddress((void**)&ph1,   g_h1);
    cudaGetSymbolAddress((void**)&peng,  g_energ);
    cudaGetSymbolAddress((void**)&pxout, g_xout);

    // 1) x0 = [emb[word], last_context]
    k_assemble_x0<<<(H2 + 255) / 256, 256>>>(word, emb, last_ctx);

    // 2) GRU layer 0 gates
    k_matvec<<<(H3 * 32 + 255) / 256, 256>>>(W_ih0, px0, b_ih0, pgi0, H3, H2);
    k_matvec<<<(H3 * 32 + 255) / 256, 256>>>(W_hh0, last_hid, b_hh0, pgh0, H3, H);
    // 3) combine -> h0
    k_gru_combine<<<(H + 255) / 256, 256>>>(pgi0, pgh0, last_hid, ph0, out_h0);

    // 4) GRU layer 1 gates
    k_matvec<<<(H3 * 32 + 255) / 256, 256>>>(W_ih1, ph0, b_ih1, pgi1, H3, H);
    k_matvec<<<(H3 * 32 + 255) / 256, 256>>>(W_hh1, last_hid + H, b_hh1, pgh1, H3, H);
    // 5) combine -> h1
    k_gru_combine<<<(H + 255) / 256, 256>>>(pgi1, pgh1, last_hid + H, ph1, out_h1);

    // 6) attention energies: enc (S x H) @ h1
    k_matvec<<<(S * 32 + 255) / 256, 256>>>(enc, ph1, (const float*)nullptr, peng, S, H);

    // 7) softmax -> attention weights (directly in d_out)
    k_attn_softmax<<<1, 1024>>>(out_attn);

    // 8) context = attn @ enc (deterministic 2-stage)
    k_ctx_partial<<<32, 1024>>>(enc, out_attn);
    k_ctx_reduce<<<(H + 255) / 256, 256>>>(out_ctx);

    // 9) vocab logits into d_out
    k_matvec<<<(VOCAB * 32 + 255) / 256, 256>>>(W_out, pxout, b_out, out_logit, VOCAB, H2);

    // 10) log_softmax
    k_lse<<<1, 1024>>>(out_logit);
    k_finalize<<<(VOCAB + 255) / 256, 256>>>(out_logit);
}